// round 4
// baseline (speedup 1.0000x reference)
#include <cuda_runtime.h>
#include <cstddef>

#define Mn   2048
#define LLn  64
#define Pp   4
#define Ssn  2
#define RPB  16
#define NTHR 256
#define NBLK (Mn/RPB)

// smem (floats): wbuf[16384] | hA[2048] | zS[8192] | ids[96 ints]
#define OFF_HA 16384
#define OFF_ZS (16384+2048)
#define OFF_ID (16384+2048+8192)
#define SMEMB  ((OFF_ID+96)*4)

__device__ float g_EWm[(size_t)LLn * Mn * 512];
__device__ float g_EWs[(size_t)LLn * Mn * 512];
__device__ float g_zL [(size_t)Mn * 512];
__device__ float g_c0[128];
__device__ float g_z1b[512];
// pre-shuffled weights: [pair P(64)][thread t(256)][4] = {W[2P][2t],W[2P+1][2t],W[2P][2t+1],W[2P+1][2t+1]}
__device__ float g_Ump[65536];
__device__ float g_Usp[65536];
__device__ float g_Wmp[65536];
__device__ float g_Wsp[65536];

typedef unsigned long long u64t;

__device__ __forceinline__ u64t f2u(float a, float b){ u64t r; asm("mov.b64 %0,{%1,%2};":"=l"(r):"f"(a),"f"(b)); return r; }
__device__ __forceinline__ float2 u2f(u64t u){ float2 v; asm("mov.b64 {%0,%1},%2;":"=f"(v.x),"=f"(v.y):"l"(u)); return v; }
__device__ __forceinline__ void fma2(u64t&a, u64t x, u64t w){ asm("fma.rn.f32x2 %0,%1,%2,%0;":"+l"(a):"l"(x),"l"(w)); }

__device__ __forceinline__ void cpa16(float* sdst, const float* gsrc){
  unsigned s=(unsigned)__cvta_generic_to_shared(sdst);
  asm volatile("cp.async.cg.shared.global [%0],[%1],16;"::"r"(s),"l"(gsrc));
}
__device__ __forceinline__ void cpcommit(){ asm volatile("cp.async.commit_group;":::"memory"); }
__device__ __forceinline__ void cpwait1(){ asm volatile("cp.async.wait_group 1;":::"memory"); }
__device__ __forceinline__ void cpwait0(){ asm volatile("cp.async.wait_group 0;":::"memory"); }

__device__ __forceinline__ float sigf(float x){ return 1.f/(1.f+__expf(-x)); }
__device__ __forceinline__ float tfast(float x){
  x = fminf(fmaxf(x,-15.f),15.f);
  float t = __expf(2.f*x);
  return (t-1.f)/(t+1.f);
}

// acc[r][c] : u64 = {sum over even k, sum over odd k} for column (2*tid+c), row r.
// Wp pre-shuffled (see above). hA [16][128] fp32 in smem.
__device__ __forceinline__ void gemm(u64t acc[RPB][2], const float* __restrict__ Wp,
    const float* xs, float* wbuf, int tid)
{
  #pragma unroll
  for(int i=0;i<8;i++) cpa16(wbuf + 4*(tid+256*i), Wp + 4*(tid+256*i));
  cpcommit();
  #pragma unroll 1
  for(int kt=0;kt<8;kt++){
    if(kt<7){
      const float* src = Wp + (kt+1)*8192;
      float* dst = wbuf + ((kt+1)&1)*8192;
      #pragma unroll
      for(int i=0;i<8;i++) cpa16(dst + 4*(tid+256*i), src + 4*(tid+256*i));
      cpcommit(); cpwait1();
    } else {
      cpwait0();
    }
    __syncthreads();
    const float* wb = wbuf + (kt&1)*8192;
    #pragma unroll
    for(int p2=0;p2<4;p2++){
      // pairs 2*p2 (k=4p2,4p2+1) and 2*p2+1 (k=4p2+2,4p2+3)
      float4 wa  = *(const float4*)(wb + ((2*p2  )*256 + tid)*4);
      float4 wbv = *(const float4*)(wb + ((2*p2+1)*256 + tid)*4);
      u64t wA0=f2u(wa.x,wa.y),  wA1=f2u(wa.z,wa.w);
      u64t wB0=f2u(wbv.x,wbv.y),wB1=f2u(wbv.z,wbv.w);
      #pragma unroll
      for(int r=0;r<RPB;r++){
        float4 xv = *(const float4*)(xs + r*128 + kt*16 + p2*4);   // broadcast
        u64t x01=f2u(xv.x,xv.y), x23=f2u(xv.z,xv.w);
        fma2(acc[r][0], x01, wA0);
        fma2(acc[r][1], x01, wA1);
        fma2(acc[r][0], x23, wB0);
        fma2(acc[r][1], x23, wB1);
      }
    }
    __syncthreads();
  }
}

__device__ __forceinline__ void zero_acc(u64t acc[RPB][2]){
  #pragma unroll
  for(int r=0;r<RPB;r++){ acc[r][0]=0ull; acc[r][1]=0ull; }
}
__device__ __forceinline__ float2 redz(const u64t a[2]){
  float2 x=u2f(a[0]), y=u2f(a[1]);
  return make_float2(x.x+x.y, y.x+y.y);
}

// gate-aligned cell phase: thread handles rows 4*rgrp..+3, dims d0,d0+1.
__device__ __forceinline__ void cell_phase(const float* zS, float* hA, float2 cst[4], int rgrp, int d0){
  #pragma unroll
  for(int rr=0;rr<4;rr++){
    int r=4*rgrp+rr;
    const float* zr = zS + r*512 + d0;
    float2 zi=*(const float2*)(zr),     zf=*(const float2*)(zr+128);
    float2 zg=*(const float2*)(zr+256), zo=*(const float2*)(zr+384);
    float2& c=cst[rr];
    c.x = sigf(zf.x)*c.x + sigf(zi.x)*tfast(zg.x);
    c.y = sigf(zf.y)*c.y + sigf(zi.y)*tfast(zg.y);
    float2 h;
    h.x = sigf(zo.x)*tfast(c.x);
    h.y = sigf(zo.y)*tfast(c.y);
    *(float2*)(hA + r*128 + d0) = h;
  }
}

__global__ void __launch_bounds__(NTHR,1) layer_kernel(int l, float* __restrict__ emb,
  const int* __restrict__ prop, const int* __restrict__ sup,
  const float* __restrict__ bm, const float* __restrict__ bs)
{
  extern __shared__ float smx[];
  float* wbuf = smx;
  float* hA   = smx + OFF_HA;
  float* zS   = smx + OFF_ZS;
  int*   ids  = (int*)(smx + OFF_ID);
  const int tid=threadIdx.x;
  const int rgrp=tid>>6, d0=(tid&63)*2;
  const int lrow0 = blockIdx.x*RPB;
  const int base  = l*Mn + lrow0;

  if(tid<64) ids[tid] = prop[lrow0*Pp + tid];
  else if(tid<96) ids[tid] = sup[lrow0*Ssn + (tid-64)];
  __syncthreads();

  u64t acc[RPB][2];
  float2 cst[4];

  // ---- member t=1: z = E_Wm[pid0] + z1b ; c_prev = c0
  {
    float2 zb = *(const float2*)(g_z1b + 2*tid);
    #pragma unroll
    for(int r=0;r<RPB;r++){
      int pid = ids[r*Pp];
      float2 e = *(const float2*)(g_EWm + (size_t)pid*512 + 2*tid);
      *(float2*)(zS + r*512 + 2*tid) = make_float2(e.x+zb.x, e.y+zb.y);
    }
  }
  __syncthreads();
  #pragma unroll
  for(int rr=0;rr<4;rr++) cst[rr] = *(const float2*)(g_c0 + d0);
  cell_phase(zS, hA, cst, rgrp, d0);
  __syncthreads();

  // ---- member t=2..4: z = E_Wm[pid_{t-1}] + h @ Um
  #pragma unroll 1
  for(int t=2;t<=4;t++){
    zero_acc(acc);
    gemm(acc, g_Ump, hA, wbuf, tid);
    #pragma unroll
    for(int r=0;r<RPB;r++){
      int pid = ids[r*Pp + (t-1)];
      float2 e = *(const float2*)(g_EWm + (size_t)pid*512 + 2*tid);
      float2 z = redz(acc[r]);
      *(float2*)(zS + r*512 + 2*tid) = make_float2(z.x+e.x, z.y+e.y);
    }
    __syncthreads();
    cell_phase(zS, hA, cst, rgrp, d0);
    __syncthreads();
  }
  // hA == h_m

  // ---- zlast = b_s + h_m @ Ws -> g_zL (own rows, own cols; reread by same thread)
  {
    float2 bsv = *(const float2*)(bs + 2*tid);
    zero_acc(acc);
    gemm(acc, g_Wsp, hA, wbuf, tid);
    #pragma unroll
    for(int r=0;r<RPB;r++){
      float2 z = redz(acc[r]);
      *(float2*)(g_zL + (size_t)(lrow0+r)*512 + 2*tid) = make_float2(z.x+bsv.x, z.y+bsv.y);
    }
  }

  // ---- super t=0: z = E_Ws[sid0], zero state
  #pragma unroll
  for(int r=0;r<RPB;r++){
    int sid = ids[64 + r*Ssn];
    float2 e = *(const float2*)(g_EWs + (size_t)sid*512 + 2*tid);
    *(float2*)(zS + r*512 + 2*tid) = e;
  }
  __syncthreads();
  #pragma unroll
  for(int rr=0;rr<4;rr++) cst[rr]=make_float2(0.f,0.f);
  cell_phase(zS, hA, cst, rgrp, d0);
  __syncthreads();

  // ---- super t=1: z = E_Ws[sid1] + h @ Us
  zero_acc(acc);
  gemm(acc, g_Usp, hA, wbuf, tid);
  #pragma unroll
  for(int r=0;r<RPB;r++){
    int sid = ids[64 + r*Ssn + 1];
    float2 e = *(const float2*)(g_EWs + (size_t)sid*512 + 2*tid);
    float2 z = redz(acc[r]);
    *(float2*)(zS + r*512 + 2*tid) = make_float2(z.x+e.x, z.y+e.y);
  }
  __syncthreads();
  cell_phase(zS, hA, cst, rgrp, d0);
  __syncthreads();

  // ---- super t=2: z = zL + h @ Us -> h_s
  zero_acc(acc);
  gemm(acc, g_Usp, hA, wbuf, tid);
  #pragma unroll
  for(int r=0;r<RPB;r++){
    float2 e = *(const float2*)(g_zL + (size_t)(lrow0+r)*512 + 2*tid);
    float2 z = redz(acc[r]);
    *(float2*)(zS + r*512 + 2*tid) = make_float2(z.x+e.x, z.y+e.y);
  }
  __syncthreads();
  cell_phase(zS, hA, cst, rgrp, d0);
  __syncthreads();

  // ---- write emb rows
  {
    float4* dst=(float4*)(emb + (size_t)base*128);
    const float4* src=(const float4*)hA;
    dst[tid]     = src[tid];
    dst[tid+256] = src[tid+256];
  }

  // ---- produce z-tables for this layer's rows
  {
    float2 bmv = *(const float2*)(bm + 2*tid);
    zero_acc(acc);
    gemm(acc, g_Wmp, hA, wbuf, tid);
    #pragma unroll
    for(int r=0;r<RPB;r++){
      float2 z = redz(acc[r]);
      *(float2*)(g_EWm + (size_t)(base+r)*512 + 2*tid) = make_float2(z.x+bmv.x, z.y+bmv.y);
    }
  }
  {
    float2 bsv = *(const float2*)(bs + 2*tid);
    zero_acc(acc);
    gemm(acc, g_Wsp, hA, wbuf, tid);
    #pragma unroll
    for(int r=0;r<RPB;r++){
      float2 z = redz(acc[r]);
      *(float2*)(g_EWs + (size_t)(base+r)*512 + 2*tid) = make_float2(z.x+bsv.x, z.y+bsv.y);
    }
  }
}

__global__ void __launch_bounds__(NTHR,1) layer0_kernel(float* __restrict__ emb,
  const int* __restrict__ names, const float* __restrict__ btab,
  const float* __restrict__ bm, const float* __restrict__ bs)
{
  extern __shared__ float smx[];
  float* wbuf=smx; float* hA=smx+OFF_HA;
  const int tid=threadIdx.x;
  const int row0 = blockIdx.x*RPB;

  for(int i=tid;i<RPB*128;i+=NTHR){
    int r=i>>7, k=i&127;
    float v = btab[names[row0+r]*128 + k];
    hA[i]=v;
    emb[(size_t)(row0+r)*128 + k]=v;
  }
  __syncthreads();

  u64t acc[RPB][2];
  {
    float2 bmv = *(const float2*)(bm + 2*tid);
    zero_acc(acc);
    gemm(acc, g_Wmp, hA, wbuf, tid);
    #pragma unroll
    for(int r=0;r<RPB;r++){
      float2 z = redz(acc[r]);
      *(float2*)(g_EWm + (size_t)(row0+r)*512 + 2*tid) = make_float2(z.x+bmv.x, z.y+bmv.y);
    }
  }
  {
    float2 bsv = *(const float2*)(bs + 2*tid);
    zero_acc(acc);
    gemm(acc, g_Wsp, hA, wbuf, tid);
    #pragma unroll
    for(int r=0;r<RPB;r++){
      float2 z = redz(acc[r]);
      *(float2*)(g_EWs + (size_t)(row0+r)*512 + 2*tid) = make_float2(z.x+bsv.x, z.y+bsv.y);
    }
  }
}

// pre-shuffle one weight matrix [128,512] into pair-packed layout
__global__ void shuf_kernel(float* __restrict__ dst, const float* __restrict__ src){
  int i = blockIdx.x*256 + threadIdx.x;  // 0..16383 = P*256 + t
  int P = i>>8, t = i&255;
  float4 v;
  v.x = src[(2*P  )*512 + 2*t  ];
  v.y = src[(2*P+1)*512 + 2*t  ];
  v.z = src[(2*P  )*512 + 2*t+1];
  v.w = src[(2*P+1)*512 + 2*t+1];
  ((float4*)dst)[i] = v;
}

// One-shot constants: z0 = em@Wm + bm -> c0, h0 -> z1b = h0@Um
__global__ void init_kernel(const float* __restrict__ em, const float* __restrict__ Wm,
                            const float* __restrict__ Um, const float* __restrict__ bm)
{
  __shared__ float z0[512]; __shared__ float h0[128]; __shared__ float ems[128];
  int t=threadIdx.x;
  if(t<128) ems[t]=em[t];
  __syncthreads();
  float s=bm[t];
  for(int k=0;k<128;k++) s += ems[k]*Wm[k*512+t];
  z0[t]=s;
  __syncthreads();
  if(t<128){
    float zi=z0[t], zg=z0[256+t], zo=z0[384+t];
    float c = (1.f/(1.f+expf(-zi)))*tanhf(zg);
    g_c0[t]=c;
    h0[t]=(1.f/(1.f+expf(-zo)))*tanhf(c);
  }
  __syncthreads();
  float s2=0.f;
  for(int k=0;k<128;k++) s2 += h0[k]*Um[k*512+t];
  g_z1b[t]=s2;
}

extern "C" void kernel_launch(void* const* d_in, const int* in_sizes, int n_in,
                              void* d_out, int out_size)
{
  const int*   names=(const int*)d_in[0];
  const int*   prop =(const int*)d_in[1];
  const int*   sup  =(const int*)d_in[2];
  const float* btab =(const float*)d_in[3];
  const float* Wm   =(const float*)d_in[4];
  const float* Um   =(const float*)d_in[5];
  const float* bm   =(const float*)d_in[6];
  const float* Ws   =(const float*)d_in[7];
  const float* Us   =(const float*)d_in[8];
  const float* bs   =(const float*)d_in[9];
  const float* em   =(const float*)d_in[10];
  float* emb=(float*)d_out;

  cudaFuncSetAttribute(layer_kernel,  cudaFuncAttributeMaxDynamicSharedMemorySize, SMEMB);
  cudaFuncSetAttribute(layer0_kernel, cudaFuncAttributeMaxDynamicSharedMemorySize, SMEMB);

  float *dUmp, *dUsp, *dWmp, *dWsp;
  cudaGetSymbolAddress((void**)&dUmp, g_Ump);
  cudaGetSymbolAddress((void**)&dUsp, g_Usp);
  cudaGetSymbolAddress((void**)&dWmp, g_Wmp);
  cudaGetSymbolAddress((void**)&dWsp, g_Wsp);

  init_kernel<<<1,512>>>(em, Wm, Um, bm);
  shuf_kernel<<<64,256>>>(dUmp, Um);
  shuf_kernel<<<64,256>>>(dUsp, Us);
  shuf_kernel<<<64,256>>>(dWmp, Wm);
  shuf_kernel<<<64,256>>>(dWsp, Ws);
  layer0_kernel<<<NBLK,NTHR,SMEMB>>>(emb, names, btab, bm, bs);
  for(int l=1;l<LLn;l++)
    layer_kernel<<<NBLK,NTHR,SMEMB>>>(l, emb,
        prop + (size_t)l*Mn*Pp, sup + (size_t)l*Mn*Ssn, bm, bs);
}

// round 5
// speedup vs baseline: 1.1014x; 1.1014x over previous
#include <cuda_runtime.h>
#include <cstddef>

#define Mn   2048
#define LLn  64
#define Pp   4
#define Ssn  2
#define RPB  8
#define NTHR 256
#define NBLK (Mn/RPB)

// smem floats: wbuf[16384] | hA[RPB*128] | ids[48]
#define OFF_HA 16384
#define OFF_ID (16384 + RPB*128)
#define SMEMB  ((OFF_ID + 48) * 4)

__device__ float g_EWm[(size_t)LLn * Mn * 512];
__device__ float g_EWs[(size_t)LLn * Mn * 512];
__device__ float g_zL [(size_t)Mn * 512];
__device__ float g_c0[128];
__device__ float g_z1b[512];

typedef unsigned long long u64t;

__device__ __forceinline__ u64t pack2(float x){ u64t r; asm("mov.b64 %0,{%1,%1};":"=l"(r):"f"(x)); return r; }
__device__ __forceinline__ u64t f2u(float a, float b){ u64t r; asm("mov.b64 %0,{%1,%2};":"=l"(r):"f"(a),"f"(b)); return r; }
__device__ __forceinline__ float2 u2f(u64t u){ float2 v; asm("mov.b64 {%0,%1},%2;":"=f"(v.x),"=f"(v.y):"l"(u)); return v; }
__device__ __forceinline__ void fma2(u64t&a, u64t x, u64t w){ asm("fma.rn.f32x2 %0,%1,%2,%0;":"+l"(a):"l"(x),"l"(w)); }

__device__ __forceinline__ void cpa16(float* sdst, const float* gsrc){
  unsigned s=(unsigned)__cvta_generic_to_shared(sdst);
  asm volatile("cp.async.cg.shared.global [%0],[%1],16;"::"r"(s),"l"(gsrc));
}
__device__ __forceinline__ void cpcommit(){ asm volatile("cp.async.commit_group;":::"memory"); }
__device__ __forceinline__ void cpwait1(){ asm volatile("cp.async.wait_group 1;":::"memory"); }
__device__ __forceinline__ void cpwait0(){ asm volatile("cp.async.wait_group 0;":::"memory"); }

__device__ __forceinline__ float sigf(float x){ return 1.f/(1.f+__expf(-x)); }
__device__ __forceinline__ float tfast(float x){
  x = fminf(fmaxf(x,-15.f),15.f);
  float t = __expf(2.f*x);
  return (t-1.f)/(t+1.f);
}

// Thread layout: 8 warps = 4 teams x 2 warps. team=wid>>1 owns rows 2*team..+1.
// Warp wsub covers hidden dims [64*wsub,+64); lane cg owns dims d=64*wsub+2cg,d+1.
// Gate g z-columns at float offset co(g) = 128*g + co0, co0 = 64*wsub+2*cg.
// acc[r][g]: u64 = z[d..d+1] of gate g, row (2*team + r).
__device__ __forceinline__ void gemm_pass(u64t acc[2][4], const float* __restrict__ Wg,
    const float* xs, float* wbuf, int tid, int co0, int tr0)
{
  #pragma unroll
  for(int i=0;i<8;i++) cpa16(wbuf + 4*(tid+256*i), Wg + 4*(tid+256*i));
  cpcommit();
  #pragma unroll 1
  for(int kt=0;kt<8;kt++){
    if(kt<7){
      const float* src = Wg + (kt+1)*8192;
      float* dst = wbuf + ((kt+1)&1)*8192;
      #pragma unroll
      for(int i=0;i<8;i++) cpa16(dst + 4*(tid+256*i), src + 4*(tid+256*i));
      cpcommit(); cpwait1();
    } else {
      cpwait0();
    }
    __syncthreads();
    const float* wb = wbuf + (kt&1)*8192;
    #pragma unroll
    for(int kb=0;kb<4;kb++){
      float4 xr0 = *(const float4*)(xs + (tr0  )*128 + kt*16 + kb*4);
      float4 xr1 = *(const float4*)(xs + (tr0+1)*128 + kt*16 + kb*4);
      #pragma unroll
      for(int kq=0;kq<4;kq++){
        const float* wrow = wb + (kb*4+kq)*512 + co0;
        u64t w0 = *(const u64t*)(wrow      );
        u64t w1 = *(const u64t*)(wrow + 128);
        u64t w2 = *(const u64t*)(wrow + 256);
        u64t w3 = *(const u64t*)(wrow + 384);
        u64t x0 = pack2((&xr0.x)[kq]);
        u64t x1 = pack2((&xr1.x)[kq]);
        fma2(acc[0][0], x0, w0); fma2(acc[0][1], x0, w1);
        fma2(acc[0][2], x0, w2); fma2(acc[0][3], x0, w3);
        fma2(acc[1][0], x1, w0); fma2(acc[1][1], x1, w1);
        fma2(acc[1][2], x1, w2); fma2(acc[1][3], x1, w3);
      }
    }
    __syncthreads();
  }
}

__device__ __forceinline__ float2 cell1(const u64t z[4], float2& c){
  float2 zi=u2f(z[0]), zf=u2f(z[1]), zg=u2f(z[2]), zo=u2f(z[3]);
  c.x = sigf(zf.x)*c.x + sigf(zi.x)*tfast(zg.x);
  c.y = sigf(zf.y)*c.y + sigf(zi.y)*tfast(zg.y);
  float2 h;
  h.x = sigf(zo.x)*tfast(c.x);
  h.y = sigf(zo.y)*tfast(c.y);
  return h;
}

__device__ __forceinline__ void acc_from_bias(u64t acc[2][4], const float* b, int co0){
  #pragma unroll
  for(int g=0;g<4;g++){
    float2 v = *(const float2*)(b + co0 + 128*g);
    u64t u = f2u(v.x,v.y);
    acc[0][g]=u; acc[1][g]=u;
  }
}

__device__ __forceinline__ void gather_row(u64t a[4], const float* tab, int id, int co0){
  const float* base = tab + (size_t)id*512 + co0;
  #pragma unroll
  for(int g=0;g<4;g++){ float2 v=*(const float2*)(base + 128*g); a[g]=f2u(v.x,v.y); }
}

__device__ __forceinline__ void write_row(float* tab, size_t nid, int co0, const u64t a[4]){
  float* base = tab + nid*512 + co0;
  #pragma unroll
  for(int g=0;g<4;g++) *(float2*)(base + 128*g) = u2f(a[g]);
}

__global__ void __launch_bounds__(NTHR,2) layer_kernel(int l, float* __restrict__ emb,
  const int* __restrict__ prop, const int* __restrict__ sup,
  const float* __restrict__ Um, const float* __restrict__ Us,
  const float* __restrict__ Wm, const float* __restrict__ Ws,
  const float* __restrict__ bm, const float* __restrict__ bs)
{
  extern __shared__ float smx[];
  float* wbuf = smx;
  float* hA   = smx + OFF_HA;
  int*   ids  = (int*)(smx + OFF_ID);
  const int tid=threadIdx.x, cg=tid&31, wid=tid>>5;
  const int team=wid>>1, wsub=wid&1;
  const int co0 = 64*wsub + 2*cg;
  const int tr0 = 2*team;
  const int lrow0 = blockIdx.x*RPB;
  const int base  = l*Mn + lrow0;

  if(tid<RPB*Pp) ids[tid] = prop[lrow0*Pp + tid];
  else if(tid<RPB*Pp+RPB*Ssn) ids[tid] = sup[lrow0*Ssn + (tid-RPB*Pp)];
  __syncthreads();

  u64t acc[2][4], zlast[2][4];
  float2 cst[2], hh;

  // ---- member t=1: z = E_Wm[pid0] + z1b, c_prev = c0
  {
    float2 zb[4];
    #pragma unroll
    for(int g=0;g<4;g++) zb[g] = *(const float2*)(g_z1b + co0 + 128*g);
    float2 c0v = *(const float2*)(g_c0 + co0);
    #pragma unroll
    for(int r=0;r<2;r++){
      gather_row(acc[r], g_EWm, ids[(tr0+r)*Pp+0], co0);
      #pragma unroll
      for(int g=0;g<4;g++){ float2 a=u2f(acc[r][g]); acc[r][g]=f2u(a.x+zb[g].x, a.y+zb[g].y); }
      cst[r]=c0v;
      hh = cell1(acc[r], cst[r]);
      *(float2*)(hA + (tr0+r)*128 + co0) = hh;
    }
  }
  __syncthreads();

  // ---- member t=2..4: z = E_Wm[pid_{t-1}] + h @ Um
  #pragma unroll 1
  for(int t=2;t<=4;t++){
    #pragma unroll
    for(int r=0;r<2;r++)
      gather_row(acc[r], g_EWm, ids[(tr0+r)*Pp + (t-1)], co0);
    gemm_pass(acc, Um, hA, wbuf, tid, co0, tr0);
    #pragma unroll
    for(int r=0;r<2;r++){
      hh = cell1(acc[r], cst[r]);
      *(float2*)(hA + (tr0+r)*128 + co0) = hh;
    }
    __syncthreads();
  }
  // hA == h_m

  // ---- zlast = b_s + h_m @ Ws  (x-contribution of super step t=2)
  acc_from_bias(zlast, bs, co0);
  gemm_pass(zlast, Ws, hA, wbuf, tid, co0, tr0);

  // ---- super t=0: z = E_Ws[sid0], zero state
  #pragma unroll
  for(int r=0;r<2;r++){
    gather_row(acc[r], g_EWs, ids[RPB*Pp + (tr0+r)*Ssn+0], co0);
    cst[r]=make_float2(0.f,0.f);
    hh = cell1(acc[r], cst[r]);
    *(float2*)(hA + (tr0+r)*128 + co0) = hh;
  }
  __syncthreads();

  // ---- super t=1: z = E_Ws[sid1] + h @ Us
  #pragma unroll
  for(int r=0;r<2;r++)
    gather_row(acc[r], g_EWs, ids[RPB*Pp + (tr0+r)*Ssn+1], co0);
  gemm_pass(acc, Us, hA, wbuf, tid, co0, tr0);
  #pragma unroll
  for(int r=0;r<2;r++){
    hh = cell1(acc[r], cst[r]);
    *(float2*)(hA + (tr0+r)*128 + co0) = hh;
  }
  __syncthreads();

  // ---- super t=2: z = zlast + h @ Us -> h_s
  gemm_pass(zlast, Us, hA, wbuf, tid, co0, tr0);
  #pragma unroll
  for(int r=0;r<2;r++){
    hh = cell1(zlast[r], cst[r]);
    *(float2*)(hA + (tr0+r)*128 + co0) = hh;
  }
  __syncthreads();

  // ---- write emb rows (coalesced from smem)
  ((float4*)(emb + (size_t)base*128))[tid] = ((const float4*)hA)[tid];

  // ---- produce z-tables for this layer's rows
  acc_from_bias(acc, bm, co0);
  gemm_pass(acc, Wm, hA, wbuf, tid, co0, tr0);
  #pragma unroll
  for(int r=0;r<2;r++) write_row(g_EWm, (size_t)(base+tr0+r), co0, acc[r]);

  acc_from_bias(acc, bs, co0);
  gemm_pass(acc, Ws, hA, wbuf, tid, co0, tr0);
  #pragma unroll
  for(int r=0;r<2;r++) write_row(g_EWs, (size_t)(base+tr0+r), co0, acc[r]);
}

__global__ void __launch_bounds__(NTHR,2) layer0_kernel(float* __restrict__ emb,
  const int* __restrict__ names, const float* __restrict__ btab,
  const float* __restrict__ Wm, const float* __restrict__ Ws,
  const float* __restrict__ bm, const float* __restrict__ bs)
{
  extern __shared__ float smx[];
  float* wbuf=smx; float* hA=smx+OFF_HA;
  const int tid=threadIdx.x, cg=tid&31, wid=tid>>5;
  const int team=wid>>1, wsub=wid&1;
  const int co0 = 64*wsub + 2*cg;
  const int tr0 = 2*team;
  const int row0 = blockIdx.x*RPB;

  for(int i=tid;i<RPB*128;i+=NTHR){
    int r=i>>7, k=i&127;
    float v = btab[names[row0+r]*128 + k];
    hA[i]=v;
    emb[(size_t)(row0+r)*128 + k]=v;
  }
  __syncthreads();

  u64t acc[2][4];
  acc_from_bias(acc, bm, co0);
  gemm_pass(acc, Wm, hA, wbuf, tid, co0, tr0);
  #pragma unroll
  for(int r=0;r<2;r++) write_row(g_EWm, (size_t)(row0+tr0+r), co0, acc[r]);

  acc_from_bias(acc, bs, co0);
  gemm_pass(acc, Ws, hA, wbuf, tid, co0, tr0);
  #pragma unroll
  for(int r=0;r<2;r++) write_row(g_EWs, (size_t)(row0+tr0+r), co0, acc[r]);
}

// One-shot constants: z0 = em@Wm + bm -> c0, h0 -> z1b = h0@Um
__global__ void init_kernel(const float* __restrict__ em, const float* __restrict__ Wm,
                            const float* __restrict__ Um, const float* __restrict__ bm)
{
  __shared__ float z0[512]; __shared__ float h0[128]; __shared__ float ems[128];
  int t=threadIdx.x;
  if(t<128) ems[t]=em[t];
  __syncthreads();
  float s=bm[t];
  for(int k=0;k<128;k++) s += ems[k]*Wm[k*512+t];
  z0[t]=s;
  __syncthreads();
  if(t<128){
    float zi=z0[t], zg=z0[256+t], zo=z0[384+t];
    float c = (1.f/(1.f+expf(-zi)))*tanhf(zg);
    g_c0[t]=c;
    h0[t]=(1.f/(1.f+expf(-zo)))*tanhf(c);
  }
  __syncthreads();
  float s2=0.f;
  for(int k=0;k<128;k++) s2 += h0[k]*Um[k*512+t];
  g_z1b[t]=s2;
}

extern "C" void kernel_launch(void* const* d_in, const int* in_sizes, int n_in,
                              void* d_out, int out_size)
{
  const int*   names=(const int*)d_in[0];
  const int*   prop =(const int*)d_in[1];
  const int*   sup  =(const int*)d_in[2];
  const float* btab =(const float*)d_in[3];
  const float* Wm   =(const float*)d_in[4];
  const float* Um   =(const float*)d_in[5];
  const float* bm   =(const float*)d_in[6];
  const float* Ws   =(const float*)d_in[7];
  const float* Us   =(const float*)d_in[8];
  const float* bs   =(const float*)d_in[9];
  const float* em   =(const float*)d_in[10];
  float* emb=(float*)d_out;

  cudaFuncSetAttribute(layer_kernel,  cudaFuncAttributeMaxDynamicSharedMemorySize, SMEMB);
  cudaFuncSetAttribute(layer0_kernel, cudaFuncAttributeMaxDynamicSharedMemorySize, SMEMB);

  init_kernel<<<1,512>>>(em, Wm, Um, bm);
  layer0_kernel<<<NBLK,NTHR,SMEMB>>>(emb, names, btab, Wm, Ws, bm, bs);
  for(int l=1;l<LLn;l++)
    layer_kernel<<<NBLK,NTHR,SMEMB>>>(l, emb,
        prop + (size_t)l*Mn*Pp, sup + (size_t)l*Mn*Ssn,
        Um, Us, Wm, Ws, bm, bs);
}